// round 3
// baseline (speedup 1.0000x reference)
#include <cuda_runtime.h>
#include <math.h>

// Problem dims
#define Bb   64
#define Tt   512
#define Dd   256
#define Hh   1024
#define Gg   4096          // 4*H
#define Mm   32768         // B*T
#define NCTA 128

// ---------------- scratch (__device__ globals; no dynamic allocation) ----------
__device__ float d_xg[(size_t)Tt * Gg * Bb];     // [t][col][b]   512 MB
__device__ float d_WhT[(size_t)Hh * Gg];         // [k][col]      16 MB
__device__ float d_WoT[(size_t)Hh * Dd];         // [h][d]        1 MB
__device__ float d_hsJ[(size_t)Hh * Mm];         // [j][m'] , m'=t*64+b   128 MB
__device__ float d_h[Hh * Bb];                   // h state, [k][b]
__device__ float d_part[2 * Gg * Bb];            // split-K partials [s][col][b]
__device__ unsigned d_bcount;
__device__ unsigned d_bgen;

// 16-FMA outer product: a over rows (i), b over cols (j)
#define FMA16(acc, a, b)                                                   \
    acc[0][0] += a.x * b.x; acc[0][1] += a.x * b.y;                        \
    acc[0][2] += a.x * b.z; acc[0][3] += a.x * b.w;                        \
    acc[1][0] += a.y * b.x; acc[1][1] += a.y * b.y;                        \
    acc[1][2] += a.y * b.z; acc[1][3] += a.y * b.w;                        \
    acc[2][0] += a.z * b.x; acc[2][1] += a.z * b.y;                        \
    acc[2][2] += a.z * b.z; acc[2][3] += a.z * b.w;                        \
    acc[3][0] += a.w * b.x; acc[3][1] += a.w * b.y;                        \
    acc[3][2] += a.w * b.z; acc[3][3] += a.w * b.w;

// ---------------- init: zero h state, reset barrier ----------------------------
__global__ void init_k()
{
    int i = blockIdx.x * blockDim.x + threadIdx.x;
    if (i < Hh * Bb) d_h[i] = 0.0f;
    if (i == 0) { d_bcount = 0u; d_bgen = 0u; }
}

// ---------------- generic 32x32 transpose into one of the weight scratches -----
// out[c][r] = in[r][c];  which==0 -> d_WhT (R=4096,C=1024), which==1 -> d_WoT
__global__ void transpose_k(const float* __restrict__ in, int R, int C, int which)
{
    __shared__ float tile[32][33];
    float* outp = which ? d_WoT : d_WhT;
    int c0 = blockIdx.x * 32;
    int r0 = blockIdx.y * 32;
    int tx = threadIdx.x, ty = threadIdx.y;
#pragma unroll
    for (int i = 0; i < 32; i += 8)
        tile[ty + i][tx] = in[(size_t)(r0 + ty + i) * C + c0 + tx];
    __syncthreads();
#pragma unroll
    for (int i = 0; i < 32; i += 8)
        outp[(size_t)(c0 + ty + i) * R + r0 + tx] = tile[tx][ty + i];
}

// ---------------- GEMM 1 (NT): xg[t][col][b] = inputs[b,t,:] . Wx[col,:] + bx ---
// A = inputs (row m = t*64+b -> offset (b*T + t)*D), B = Wx [4096][256]
__global__ void __launch_bounds__(256) gemm_xg(
    const float* __restrict__ A, const float* __restrict__ Bw,
    const float* __restrict__ bias)
{
    __shared__ __align__(16) float As[16][68];
    __shared__ __align__(16) float Bs[16][68];
    int tid = threadIdx.x;
    int n0 = blockIdx.x * 64;
    int m0 = blockIdx.y * 64;
    int t0 = m0 >> 6;                 // m0 is a multiple of 64 -> fixed t, b = row
    int kk = tid & 15, mq = tid >> 4;
    int mg = tid & 15, ng = tid >> 4;

    float ar[4], br[4];
#pragma unroll
    for (int p = 0; p < 4; p++) {
        int r = p * 16 + mq;
        ar[p] = A[((size_t)r * Tt + t0) * Dd + kk];
        br[p] = Bw[(size_t)(n0 + r) * Dd + kk];
    }

    float acc[4][4] = {};
    for (int k0 = 0; k0 < Dd; k0 += 16) {
        __syncthreads();
#pragma unroll
        for (int p = 0; p < 4; p++) {
            As[kk][p * 16 + mq] = ar[p];
            Bs[kk][p * 16 + mq] = br[p];
        }
        __syncthreads();
        if (k0 + 16 < Dd) {
#pragma unroll
            for (int p = 0; p < 4; p++) {
                int r = p * 16 + mq;
                ar[p] = A[((size_t)r * Tt + t0) * Dd + k0 + 16 + kk];
                br[p] = Bw[(size_t)(n0 + r) * Dd + k0 + 16 + kk];
            }
        }
#pragma unroll
        for (int q = 0; q < 16; q++) {
            float4 a = *(const float4*)&As[q][mg * 4];
            float4 b = *(const float4*)&Bs[q][ng * 4];
            FMA16(acc, a, b);
        }
    }
#pragma unroll
    for (int j = 0; j < 4; j++) {
        int n = n0 + ng * 4 + j;
        float bv = bias[n];
        float4 v = make_float4(acc[0][j] + bv, acc[1][j] + bv,
                               acc[2][j] + bv, acc[3][j] + bv);
        *(float4*)&d_xg[((size_t)t0 * Gg + n) * Bb + mg * 4] = v;
    }
}

// ---------------- software grid barrier ----------------------------------------
__device__ __forceinline__ void grid_sync()
{
    __syncthreads();
    if (threadIdx.x == 0) {
        __threadfence();
        volatile unsigned* vg = &d_bgen;
        unsigned g = *vg;
        unsigned prev = atomicAdd(&d_bcount, 1u);
        if (prev == NCTA - 1) {
            d_bcount = 0u;
            __threadfence();
            atomicAdd(&d_bgen, 1u);
        } else {
            while (*vg == g) { __nanosleep(64); }
        }
        __threadfence();
    }
    __syncthreads();
}

__device__ __forceinline__ float sigm(float x) { return 1.0f / (1.0f + expf(-x)); }

// ---------------- persistent LSTM recurrence -----------------------------------
// 128 CTAs x 256 threads.  Per step:
//  Phase A: CTA(s,cb): partial[s][col][b] = sum_{k in half s} h[k][b]*WhT[k][col]
//  Phase B: pointwise gates -> c (registers), h -> d_h [k][b], hs -> d_hsJ [j][m']
__global__ void __launch_bounds__(256, 1) lstm_k(const float* __restrict__ bh)
{
    __shared__ __align__(16) float As[16 * 64];
    __shared__ __align__(16) float Bs[16 * 64];
    int tid = threadIdx.x;
    int cta = blockIdx.x;
    int s   = cta >> 6;            // k-split 0/1
    int cb  = cta & 63;            // column block
    int kbase = s * 512;
    int nbase = cb * 64;
    int mg = tid & 15, ng = tid >> 4;
    int lk = tid >> 4, lc = (tid & 15) * 4;
    // Phase B ownership: (b, j) fixed per thread across all steps -> c in regs
    int pb  = tid & 63;
    int pj0 = cta * 8 + (tid >> 6);
    int pj1 = pj0 + 4;
    float c0s = 0.0f, c1s = 0.0f;

    for (int t = 0; t < Tt; t++) {
        float acc[4][4] = {};
        // prefetch first k-tile (h tile is a contiguous 1024-float block)
        float4 av = __ldcg((const float4*)&d_h[kbase * 64] + tid);
        float4 bv = *(const float4*)&d_WhT[(size_t)(kbase + lk) * Gg + nbase + lc];
        for (int k0 = 0; k0 < 512; k0 += 16) {
            __syncthreads();
            *(float4*)&As[tid * 4]      = av;
            *(float4*)&Bs[lk * 64 + lc] = bv;
            __syncthreads();
            if (k0 + 16 < 512) {
                av = __ldcg((const float4*)&d_h[(kbase + k0 + 16) * 64] + tid);
                bv = *(const float4*)&d_WhT[(size_t)(kbase + k0 + 16 + lk) * Gg + nbase + lc];
            }
#pragma unroll
            for (int q = 0; q < 16; q++) {
                float4 a = *(const float4*)&As[q * 64 + mg * 4];
                float4 b = *(const float4*)&Bs[q * 64 + ng * 4];
                FMA16(acc, a, b);
            }
        }
        // write split-K partials [s][col][b]
#pragma unroll
        for (int j = 0; j < 4; j++) {
            int col = nbase + ng * 4 + j;
            float4 v = make_float4(acc[0][j], acc[1][j], acc[2][j], acc[3][j]);
            __stcg((float4*)&d_part[((size_t)s * Gg + col) * 64 + mg * 4], v);
        }
        grid_sync();

        // Phase B: two (b,j) pairs per thread
#pragma unroll
        for (int pp = 0; pp < 2; pp++) {
            int j = pp ? pj1 : pj0;
            float cprev = pp ? c1s : c0s;
            size_t xb = ((size_t)t * Gg) * Bb;
            int ci = j, cf = Hh + j, cg = 2 * Hh + j, co = 3 * Hh + j;
            float gi = d_xg[xb + (size_t)ci * Bb + pb] + bh[ci]
                     + __ldcg(&d_part[(size_t)ci * 64 + pb])
                     + __ldcg(&d_part[((size_t)Gg + ci) * 64 + pb]);
            float gf = d_xg[xb + (size_t)cf * Bb + pb] + bh[cf]
                     + __ldcg(&d_part[(size_t)cf * 64 + pb])
                     + __ldcg(&d_part[((size_t)Gg + cf) * 64 + pb]);
            float gg = d_xg[xb + (size_t)cg * Bb + pb] + bh[cg]
                     + __ldcg(&d_part[(size_t)cg * 64 + pb])
                     + __ldcg(&d_part[((size_t)Gg + cg) * 64 + pb]);
            float go = d_xg[xb + (size_t)co * Bb + pb] + bh[co]
                     + __ldcg(&d_part[(size_t)co * 64 + pb])
                     + __ldcg(&d_part[((size_t)Gg + co) * 64 + pb]);
            float si = sigm(gi), sf = sigm(gf), sg = sigm(gg), so = sigm(go);
            float cnew = cprev * sf + si * sg;          // NOTE: sigmoid cell gate
            float hnew = so * tanhf(cnew);
            if (pp) c1s = cnew; else c0s = cnew;
            __stcg(&d_h[j * 64 + pb], hnew);
            d_hsJ[((size_t)j * Tt + t) * 64 + pb] = hnew;
        }
        grid_sync();
    }
}

// ---------------- GEMM 3 (TN): out[b][t][d] = hs . WoutT + bout -----------------
// AT = d_hsJ [j][m'] (stride M), BT = d_WoT [j][d] (stride D), m' = t*64+b
__global__ void __launch_bounds__(256) gemm_out(
    const float* __restrict__ bias, float* __restrict__ outp)
{
    __shared__ __align__(16) float As[16 * 64];
    __shared__ __align__(16) float Bs[16 * 64];
    int tid = threadIdx.x;
    int n0 = blockIdx.x * 64;      // d
    int m0 = blockIdx.y * 64;      // m'
    int t0 = m0 >> 6;
    int lk = tid >> 4, lc = (tid & 15) * 4;
    int mg = tid & 15, ng = tid >> 4;

    float4 av = *(const float4*)&d_hsJ[(size_t)lk * Mm + m0 + lc];
    float4 bv = *(const float4*)&d_WoT[(size_t)lk * Dd + n0 + lc];

    float acc[4][4] = {};
    for (int k0 = 0; k0 < Hh; k0 += 16) {
        __syncthreads();
        *(float4*)&As[lk * 64 + lc] = av;
        *(float4*)&Bs[lk * 64 + lc] = bv;
        __syncthreads();
        if (k0 + 16 < Hh) {
            av = *(const float4*)&d_hsJ[(size_t)(k0 + 16 + lk) * Mm + m0 + lc];
            bv = *(const float4*)&d_WoT[(size_t)(k0 + 16 + lk) * Dd + n0 + lc];
        }
#pragma unroll
        for (int q = 0; q < 16; q++) {
            float4 a = *(const float4*)&As[q * 64 + mg * 4];
            float4 b = *(const float4*)&Bs[q * 64 + ng * 4];
            FMA16(acc, a, b);
        }
    }
    float4 b4 = *(const float4*)&bias[n0 + ng * 4];
#pragma unroll
    for (int i = 0; i < 4; i++) {
        int b = mg * 4 + i;
        float4 v = make_float4(acc[i][0] + b4.x, acc[i][1] + b4.y,
                               acc[i][2] + b4.z, acc[i][3] + b4.w);
        *(float4*)&outp[((size_t)b * Tt + t0) * Dd + n0 + ng * 4] = v;
    }
}

// ---------------- hidden = tanh(hs), transposed [j][m'] -> [b][t][j] ------------
__global__ void tanhT_k(float* __restrict__ outH)
{
    __shared__ float tile[32][33];
    int m0 = blockIdx.x * 32;      // m' tile (t fixed within tile: 32 | 64)
    int j0 = blockIdx.y * 32;
    int tx = threadIdx.x, ty = threadIdx.y;
#pragma unroll
    for (int i = 0; i < 32; i += 8)
        tile[ty + i][tx] = d_hsJ[(size_t)(j0 + ty + i) * Mm + m0 + tx];
    __syncthreads();
    int t0 = m0 >> 6;
    int bbase = m0 & 63;
#pragma unroll
    for (int i = 0; i < 32; i += 8) {
        int mp = ty + i;
        int b = bbase + mp;
        outH[((size_t)b * Tt + t0) * Hh + j0 + tx] = tanhf(tile[tx][mp]);
    }
}

// ---------------- launch --------------------------------------------------------
extern "C" void kernel_launch(void* const* d_in, const int* in_sizes, int n_in,
                              void* d_out, int out_size)
{
    (void)in_sizes; (void)n_in; (void)out_size;
    const float* inp = (const float*)d_in[0];
    const float* Wx  = (const float*)d_in[1];
    const float* bx  = (const float*)d_in[2];
    const float* Wh  = (const float*)d_in[3];
    const float* bh  = (const float*)d_in[4];
    const float* Wo  = (const float*)d_in[5];
    const float* bo  = (const float*)d_in[6];
    float* out = (float*)d_out;
    float* outHidden = out + (size_t)Bb * Tt * Dd;

    init_k<<<256, 256>>>();
    transpose_k<<<dim3(Hh / 32, Gg / 32), dim3(32, 8)>>>(Wh, Gg, Hh, 0);
    transpose_k<<<dim3(Hh / 32, Dd / 32), dim3(32, 8)>>>(Wo, Dd, Hh, 1);
    gemm_xg<<<dim3(Gg / 64, Mm / 64), 256>>>(inp, Wx, bx);
    lstm_k<<<NCTA, 256>>>(bh);
    gemm_out<<<dim3(Dd / 64, Mm / 64), 256>>>(bo, out);
    tanhT_k<<<dim3(Mm / 32, Hh / 32), dim3(32, 8)>>>(outHidden);
}

// round 4
// speedup vs baseline: 1.0739x; 1.0739x over previous
#include <cuda_runtime.h>
#include <math.h>

// Problem dims
#define Bb   64
#define Tt   512
#define Dd   256
#define Hh   1024
#define Gg   4096          // 4*H
#define Mm   32768         // B*T
#define NCTA 128

// ---------------- scratch (__device__ globals; no dynamic allocation) ----------
__device__ float d_xg[(size_t)Tt * Hh * 4 * Bb];  // [t][j][gate][b]   512 MB
__device__ float d_WhT[(size_t)Hh * Gg];          // [k][col'] col'=(j>>3)*32+(j&7)*4+g
__device__ float d_WoT[(size_t)Hh * Dd];          // [h][d]
__device__ float d_hsJ[(size_t)Hh * Mm];          // [j][m'] , m'=t*64+b   128 MB
__device__ float d_h2[2 * Hh * Bb];               // double-buffered h, [buf][k][b]
__device__ unsigned d_bcount;
__device__ unsigned d_bgen;

// ---------- packed fp32x2 helpers (Blackwell dual fp32 pipe) --------------------
#define FMA2(d, a, b) asm("fma.rn.f32x2 %0, %1, %2, %0;" : "+l"(d) : "l"(a), "l"(b))
#define DUP2(d, s)    asm("mov.b64 %0, {%1, %1};"        : "=l"(d) : "f"(s))
#define UNPK2(lo, hi, v) asm("mov.b64 {%0, %1}, %2;" : "=f"(lo), "=f"(hi) : "l"(v))

typedef unsigned long long u64;

// ---------------- init: zero h state, reset barrier ----------------------------
__global__ void init_k()
{
    int i = blockIdx.x * blockDim.x + threadIdx.x;
    if (i < 2 * Hh * Bb) d_h2[i] = 0.0f;
    if (i == 0) { d_bcount = 0u; d_bgen = 0u; }
}

// ---------------- transposes ----------------------------------------------------
// which==0: Wh [4096][1024] -> d_WhT[k][col'] with gate-quadruple permutation
// which==1: Wout [256][1024] -> d_WoT[h][d] plain
__global__ void transpose_k(const float* __restrict__ in, int R, int C, int which)
{
    __shared__ float tile[32][33];
    int c0 = blockIdx.x * 32;
    int r0 = blockIdx.y * 32;
    int tx = threadIdx.x, ty = threadIdx.y;
#pragma unroll
    for (int i = 0; i < 32; i += 8)
        tile[ty + i][tx] = in[(size_t)(r0 + ty + i) * C + c0 + tx];
    __syncthreads();
    if (which == 0) {
        int r = r0 + tx;                  // original gate row
        int g = r >> 10, j = r & 1023;
        int nc = ((j >> 3) << 5) + ((j & 7) << 2) + g;   // permuted column
#pragma unroll
        for (int i = 0; i < 32; i += 8)
            d_WhT[(size_t)(c0 + ty + i) * Gg + nc] = tile[tx][ty + i];
    } else {
#pragma unroll
        for (int i = 0; i < 32; i += 8)
            d_WoT[(size_t)(c0 + ty + i) * R + r0 + tx] = tile[tx][ty + i];
    }
}

// ---------------- GEMM 1 (NT, f32x2): xg[t][j][g][b] = inputs . Wx^T + bx + bh --
__global__ void __launch_bounds__(256) gemm_xg(
    const float* __restrict__ A, const float* __restrict__ Bw,
    const float* __restrict__ bx, const float* __restrict__ bh)
{
    __shared__ __align__(16) float As[16][68];
    __shared__ __align__(16) float Bs[16][68];
    int tid = threadIdx.x;
    int n0 = blockIdx.x * 64;
    int m0 = blockIdx.y * 64;
    int t0 = m0 >> 6;                 // fixed t per block, b = row in tile
    int kk = tid & 15, mq = tid >> 4;
    int mg = tid & 15, ng = tid >> 4;

    float ar[4], br[4];
#pragma unroll
    for (int p = 0; p < 4; p++) {
        int r = p * 16 + mq;
        ar[p] = A[((size_t)r * Tt + t0) * Dd + kk];
        br[p] = Bw[(size_t)(n0 + r) * Dd + kk];
    }

    u64 acc[2][4];
#pragma unroll
    for (int p = 0; p < 2; p++)
#pragma unroll
        for (int q = 0; q < 4; q++) acc[p][q] = 0ull;

    for (int k0 = 0; k0 < Dd; k0 += 16) {
        __syncthreads();
#pragma unroll
        for (int p = 0; p < 4; p++) {
            As[kk][p * 16 + mq] = ar[p];
            Bs[kk][p * 16 + mq] = br[p];
        }
        __syncthreads();
        if (k0 + 16 < Dd) {
#pragma unroll
            for (int p = 0; p < 4; p++) {
                int r = p * 16 + mq;
                ar[p] = A[((size_t)r * Tt + t0) * Dd + k0 + 16 + kk];
                br[p] = Bw[(size_t)(n0 + r) * Dd + k0 + 16 + kk];
            }
        }
#pragma unroll
        for (int q = 0; q < 16; q++) {
            ulonglong2 a2 = *(const ulonglong2*)&As[q][mg * 4];
            float4 b4 = *(const float4*)&Bs[q][ng * 4];
            u64 bb0, bb1, bb2, bb3;
            DUP2(bb0, b4.x); DUP2(bb1, b4.y); DUP2(bb2, b4.z); DUP2(bb3, b4.w);
            FMA2(acc[0][0], a2.x, bb0); FMA2(acc[1][0], a2.y, bb0);
            FMA2(acc[0][1], a2.x, bb1); FMA2(acc[1][1], a2.y, bb1);
            FMA2(acc[0][2], a2.x, bb2); FMA2(acc[1][2], a2.y, bb2);
            FMA2(acc[0][3], a2.x, bb3); FMA2(acc[1][3], a2.y, bb3);
        }
    }
#pragma unroll
    for (int jj = 0; jj < 4; jj++) {
        int n = n0 + ng * 4 + jj;
        int g = n >> 10, j = n & 1023;
        float bv = bx[n] + bh[n];
        float v0, v1, v2, v3;
        UNPK2(v0, v1, acc[0][jj]);
        UNPK2(v2, v3, acc[1][jj]);
        float4 v = make_float4(v0 + bv, v1 + bv, v2 + bv, v3 + bv);
        *(float4*)&d_xg[((((size_t)t0 * Hh + j) << 2) + g) * Bb + mg * 4] = v;
    }
}

// ---------------- software grid barrier ----------------------------------------
__device__ __forceinline__ void grid_sync()
{
    __syncthreads();
    if (threadIdx.x == 0) {
        __threadfence();
        volatile unsigned* vg = &d_bgen;
        unsigned g = *vg;
        unsigned prev = atomicAdd(&d_bcount, 1u);
        if (prev == NCTA - 1) {
            d_bcount = 0u;
            __threadfence();
            atomicAdd(&d_bgen, 1u);
        } else {
            while (*vg == g) { __nanosleep(64); }
        }
        __threadfence();
    }
    __syncthreads();
}

__device__ __forceinline__ float sigm(float x) { return 1.0f / (1.0f + expf(-x)); }

// ---------------- persistent fused LSTM recurrence ------------------------------
// 128 CTAs x 128 threads. CTA owns j in [cta*8, cta*8+8), ALL 4 gates, full K.
// Thread (mg,ng): batches mg*4..+3, j = cta*8+ng, gates = its 4 accumulator cols.
// One grid barrier per step; h double-buffered; c lives in registers.
__global__ void __launch_bounds__(128, 1) lstm_k()
{
    __shared__ __align__(16) float As[2][32 * 64];   // h tile   [k][b]
    __shared__ __align__(16) float Bs[2][32 * 32];   // Wh tile  [k][col']
    const int tid = threadIdx.x;
    const int cta = blockIdx.x;
    const int mg = tid & 15;        // batch quad
    const int ng = tid >> 4;        // jj (0..7)
    const int j  = cta * 8 + ng;
    const float* Wbase = d_WhT + cta * 32;
    float c[4] = {0.f, 0.f, 0.f, 0.f};

    for (int t = 0; t < Tt; t++) {
        const float* hcur = d_h2 + (size_t)(t & 1) * (Hh * Bb);
        float*       hnxt = d_h2 + (size_t)((t + 1) & 1) * (Hh * Bb);

        // prefetch xg for this thread's (j, batches): 4 gates x float4
        float4 xgv[4];
#pragma unroll
        for (int g = 0; g < 4; g++)
            xgv[g] = *(const float4*)&d_xg[((((size_t)t * Hh + j) << 2) + g) * Bb + mg * 4];

        u64 acc[2][4];
#pragma unroll
        for (int p = 0; p < 2; p++)
#pragma unroll
            for (int q = 0; q < 4; q++) acc[p][q] = 0ull;

        // preload k-tile 0 into registers
        float4 ag[4]; float4 bg[2];
#pragma unroll
        for (int p = 0; p < 4; p++)
            ag[p] = __ldcg((const float4*)hcur + p * 128 + tid);
#pragma unroll
        for (int p = 0; p < 2; p++) {
            int q = p * 128 + tid;
            bg[p] = *(const float4*)&Wbase[(size_t)(q >> 3) * Gg + ((q & 7) << 2)];
        }

#pragma unroll 1
        for (int kt = 0; kt < 32; kt++) {
            const int buf = kt & 1;
            // stage regs -> smem
#pragma unroll
            for (int p = 0; p < 4; p++)
                *((float4*)As[buf] + p * 128 + tid) = ag[p];
#pragma unroll
            for (int p = 0; p < 2; p++)
                *((float4*)Bs[buf] + p * 128 + tid) = bg[p];
            __syncthreads();
            // prefetch next k-tile
            if (kt < 31) {
                const int k0 = (kt + 1) * 32;
#pragma unroll
                for (int p = 0; p < 4; p++)
                    ag[p] = __ldcg((const float4*)(hcur + k0 * 64) + p * 128 + tid);
#pragma unroll
                for (int p = 0; p < 2; p++) {
                    int q = p * 128 + tid;
                    bg[p] = *(const float4*)&Wbase[(size_t)(k0 + (q >> 3)) * Gg + ((q & 7) << 2)];
                }
            }
            // compute 32 k (packed fp32x2: 8 FFMA2 per k)
#pragma unroll
            for (int k = 0; k < 32; k++) {
                ulonglong2 a2 = *(const ulonglong2*)&As[buf][k * 64 + mg * 4];
                float4 b4 = *(const float4*)&Bs[buf][k * 32 + ng * 4];
                u64 bb0, bb1, bb2, bb3;
                DUP2(bb0, b4.x); DUP2(bb1, b4.y); DUP2(bb2, b4.z); DUP2(bb3, b4.w);
                FMA2(acc[0][0], a2.x, bb0); FMA2(acc[1][0], a2.y, bb0);
                FMA2(acc[0][1], a2.x, bb1); FMA2(acc[1][1], a2.y, bb1);
                FMA2(acc[0][2], a2.x, bb2); FMA2(acc[1][2], a2.y, bb2);
                FMA2(acc[0][3], a2.x, bb3); FMA2(acc[1][3], a2.y, bb3);
            }
        }

        // ---- fused pointwise: gates fully local to this thread ----
        float ga[4][4];   // [batch i][gate g]
#pragma unroll
        for (int g = 0; g < 4; g++) {
            UNPK2(ga[0][g], ga[1][g], acc[0][g]);
            UNPK2(ga[2][g], ga[3][g], acc[1][g]);
        }
        const float* xf = (const float*)xgv;   // xf[g*4 + i]
        float hout[4];
#pragma unroll
        for (int i = 0; i < 4; i++) {
            float si = sigm(ga[i][0] + xf[0 * 4 + i]);
            float sf = sigm(ga[i][1] + xf[1 * 4 + i]);
            float sg = sigm(ga[i][2] + xf[2 * 4 + i]);
            float so = sigm(ga[i][3] + xf[3 * 4 + i]);
            c[i] = c[i] * sf + si * sg;        // NOTE: sigmoid cell gate (per ref)
            hout[i] = so * tanhf(c[i]);
        }
        float4 hv = make_float4(hout[0], hout[1], hout[2], hout[3]);
        __stcg((float4*)&hnxt[j * 64 + mg * 4], hv);
        *(float4*)&d_hsJ[((size_t)j * Tt + t) * 64 + mg * 4] = hv;

        grid_sync();
    }
}

// ---------------- GEMM 3 (TN): out[b][t][d] = hs . WoutT + bout -----------------
__global__ void __launch_bounds__(256) gemm_out(
    const float* __restrict__ bias, float* __restrict__ outp)
{
    __shared__ __align__(16) float As[16 * 64];
    __shared__ __align__(16) float Bs[16 * 64];
    int tid = threadIdx.x;
    int n0 = blockIdx.x * 64;      // d
    int m0 = blockIdx.y * 64;      // m'
    int t0 = m0 >> 6;
    int lk = tid >> 4, lc = (tid & 15) * 4;
    int mg = tid & 15, ng = tid >> 4;

    float4 av = *(const float4*)&d_hsJ[(size_t)lk * Mm + m0 + lc];
    float4 bv = *(const float4*)&d_WoT[(size_t)lk * Dd + n0 + lc];

    u64 acc[2][4];
#pragma unroll
    for (int p = 0; p < 2; p++)
#pragma unroll
        for (int q = 0; q < 4; q++) acc[p][q] = 0ull;

    for (int k0 = 0; k0 < Hh; k0 += 16) {
        __syncthreads();
        *(float4*)&As[lk * 64 + lc] = av;
        *(float4*)&Bs[lk * 64 + lc] = bv;
        __syncthreads();
        if (k0 + 16 < Hh) {
            av = *(const float4*)&d_hsJ[(size_t)(k0 + 16 + lk) * Mm + m0 + lc];
            bv = *(const float4*)&d_WoT[(size_t)(k0 + 16 + lk) * Dd + n0 + lc];
        }
#pragma unroll
        for (int q = 0; q < 16; q++) {
            ulonglong2 a2 = *(const ulonglong2*)&As[q * 64 + mg * 4];
            float4 b4 = *(const float4*)&Bs[q * 64 + ng * 4];
            u64 bb0, bb1, bb2, bb3;
            DUP2(bb0, b4.x); DUP2(bb1, b4.y); DUP2(bb2, b4.z); DUP2(bb3, b4.w);
            FMA2(acc[0][0], a2.x, bb0); FMA2(acc[1][0], a2.y, bb0);
            FMA2(acc[0][1], a2.x, bb1); FMA2(acc[1][1], a2.y, bb1);
            FMA2(acc[0][2], a2.x, bb2); FMA2(acc[1][2], a2.y, bb2);
            FMA2(acc[0][3], a2.x, bb3); FMA2(acc[1][3], a2.y, bb3);
        }
    }
    float4 b4 = *(const float4*)&bias[n0 + ng * 4];
    float r[4][4];
#pragma unroll
    for (int q = 0; q < 4; q++) {
        UNPK2(r[0][q], r[1][q], acc[0][q]);
        UNPK2(r[2][q], r[3][q], acc[1][q]);
    }
#pragma unroll
    for (int i = 0; i < 4; i++) {
        int b = mg * 4 + i;
        float4 v = make_float4(r[i][0] + b4.x, r[i][1] + b4.y,
                               r[i][2] + b4.z, r[i][3] + b4.w);
        *(float4*)&outp[((size_t)b * Tt + t0) * Dd + n0 + ng * 4] = v;
    }
}

// ---------------- hidden = tanh(hs), [j][m'] -> [b][t][j] ----------------------
__global__ void tanhT_k(float* __restrict__ outH)
{
    __shared__ float tile[32][33];
    int m0 = blockIdx.x * 32;
    int j0 = blockIdx.y * 32;
    int tx = threadIdx.x, ty = threadIdx.y;
#pragma unroll
    for (int i = 0; i < 32; i += 8)
        tile[ty + i][tx] = d_hsJ[(size_t)(j0 + ty + i) * Mm + m0 + tx];
    __syncthreads();
    int t0 = m0 >> 6;
    int bbase = m0 & 63;
#pragma unroll
    for (int i = 0; i < 32; i += 8) {
        int mp = ty + i;
        int b = bbase + mp;
        outH[((size_t)b * Tt + t0) * Hh + j0 + tx] = tanhf(tile[tx][mp]);
    }
}

// ---------------- launch --------------------------------------------------------
extern "C" void kernel_launch(void* const* d_in, const int* in_sizes, int n_in,
                              void* d_out, int out_size)
{
    (void)in_sizes; (void)n_in; (void)out_size;
    const float* inp = (const float*)d_in[0];
    const float* Wx  = (const float*)d_in[1];
    const float* bx  = (const float*)d_in[2];
    const float* Wh  = (const float*)d_in[3];
    const float* bh  = (const float*)d_in[4];
    const float* Wo  = (const float*)d_in[5];
    const float* bo  = (const float*)d_in[6];
    float* out = (float*)d_out;
    float* outHidden = out + (size_t)Bb * Tt * Dd;

    init_k<<<512, 256>>>();
    transpose_k<<<dim3(Hh / 32, Gg / 32), dim3(32, 8)>>>(Wh, Gg, Hh, 0);
    transpose_k<<<dim3(Hh / 32, Dd / 32), dim3(32, 8)>>>(Wo, Dd, Hh, 1);
    gemm_xg<<<dim3(Gg / 64, Mm / 64), 256>>>(inp, Wx, bx, bh);
    lstm_k<<<NCTA, 128>>>();
    gemm_out<<<dim3(Dd / 64, Mm / 64), 256>>>(bo, out);
    tanhT_k<<<dim3(Mm / 32, Hh / 32), dim3(32, 8)>>>(outHidden);
}

// round 5
// speedup vs baseline: 1.7247x; 1.6060x over previous
#include <cuda_runtime.h>
#include <math.h>

// Problem dims
#define Bb   64
#define Tt   512
#define Dd   256
#define Hh   1024
#define Gg   4096          // 4*H
#define Mm   32768         // B*T
#define NCTA 128

// ---------------- scratch (__device__ globals; no dynamic allocation) ----------
__device__ float d_xg[(size_t)Tt * Hh * 4 * Bb];  // [t][j][gate][b]   512 MB
__device__ float d_Af[(size_t)Gg * Hh];           // packed tf32 A-fragments, 16 MB
__device__ float d_WoT[(size_t)Hh * Dd];          // [h][d]
__device__ float d_hsJ[(size_t)Hh * Mm];          // [j][m'] , m'=t*64+b   128 MB
__device__ float d_h2[2 * Hh * Bb];               // double-buffered h (tf32 bits), [buf][k][b]
__device__ unsigned d_bcount;
__device__ unsigned d_bgen;

// ---------- packed fp32x2 helpers (kept for gemm_xg / gemm_out) -----------------
#define FMA2(d, a, b) asm("fma.rn.f32x2 %0, %1, %2, %0;" : "+l"(d) : "l"(a), "l"(b))
#define DUP2(d, s)    asm("mov.b64 %0, {%1, %1};"        : "=l"(d) : "f"(s))
#define UNPK2(lo, hi, v) asm("mov.b64 {%0, %1}, %2;" : "=f"(lo), "=f"(hi) : "l"(v))
typedef unsigned long long u64;

__device__ __forceinline__ unsigned tf32r(float x)
{
    unsigned u;
    asm("cvt.rna.tf32.f32 %0, %1;" : "=r"(u) : "f"(x));
    return u;
}

// tf32 mma: D(m16n8) += A(m16k8) * B(k8n8)
#define MMA_TF32(d, a0, a1, a2, a3, b0, b1)                                     \
    asm volatile("mma.sync.aligned.m16n8k8.row.col.f32.tf32.tf32.f32 "          \
                 "{%0,%1,%2,%3}, {%4,%5,%6,%7}, {%8,%9}, {%0,%1,%2,%3};"        \
                 : "+f"(d[0]), "+f"(d[1]), "+f"(d[2]), "+f"(d[3])               \
                 : "r"(a0), "r"(a1), "r"(a2), "r"(a3), "r"(b0), "r"(b1))

// ---------------- init: zero h state, reset barrier ----------------------------
__global__ void init_k()
{
    int i = blockIdx.x * blockDim.x + threadIdx.x;
    if (i < 2 * Hh * Bb) d_h2[i] = 0.0f;
    if (i == 0) { d_bcount = 0u; d_bgen = 0u; }
}

// ---------------- Wout transpose: d_WoT[h][d] = Wout[d][h] ----------------------
__global__ void transpose_wo(const float* __restrict__ in)
{
    __shared__ float tile[32][33];
    int c0 = blockIdx.x * 32;            // h
    int r0 = blockIdx.y * 32;            // d
    int tx = threadIdx.x, ty = threadIdx.y;
#pragma unroll
    for (int i = 0; i < 32; i += 8)
        tile[ty + i][tx] = in[(size_t)(r0 + ty + i) * Hh + c0 + tx];
    __syncthreads();
#pragma unroll
    for (int i = 0; i < 32; i += 8)
        d_WoT[(size_t)(c0 + ty + i) * Dd + r0 + tx] = tile[tx][ty + i];
}

// ---------------- pack Wh into per-warp tf32 A-fragments ------------------------
// Fragment float4 index i: lane=i&31, kc=(i>>5)&127, ms=(i>>12)&1, cb=i>>13
// CTA cb owns local cols m=0..31: j = cb*8 + (m>>2), gate = m&3.
// A[m][k] = Wh[gate*1024 + j][k].  m16n8k8 A frag: a0=[g][tig] a1=[g+8][tig]
// a2=[g][tig+4] a3=[g+8][tig+4], rows within strip ms*16.., k = kc*8 + ...
__global__ void pack_af(const float* __restrict__ Wh)
{
    size_t i = (size_t)blockIdx.x * blockDim.x + threadIdx.x;   // 1,048,576
    int lane = i & 31;
    int kc   = (i >> 5) & 127;
    int ms   = (i >> 12) & 1;
    int cb   = (int)(i >> 13);
    int g = lane >> 2, tig = lane & 3;
    int m1 = ms * 16 + g, m2 = m1 + 8;
    int r1 = (m1 & 3) * Hh + cb * 8 + (m1 >> 2);
    int r2 = (m2 & 3) * Hh + cb * 8 + (m2 >> 2);
    int k0 = kc * 8;
    float4 v;
    v.x = __uint_as_float(tf32r(Wh[(size_t)r1 * Hh + k0 + tig]));
    v.y = __uint_as_float(tf32r(Wh[(size_t)r2 * Hh + k0 + tig]));
    v.z = __uint_as_float(tf32r(Wh[(size_t)r1 * Hh + k0 + tig + 4]));
    v.w = __uint_as_float(tf32r(Wh[(size_t)r2 * Hh + k0 + tig + 4]));
    ((float4*)d_Af)[i] = v;
}

// ---------------- GEMM 1 (NT, f32x2): xg[t][j][g][b] = inputs . Wx^T + bx + bh --
__global__ void __launch_bounds__(256) gemm_xg(
    const float* __restrict__ A, const float* __restrict__ Bw,
    const float* __restrict__ bx, const float* __restrict__ bh)
{
    __shared__ __align__(16) float As[16][68];
    __shared__ __align__(16) float Bs[16][68];
    int tid = threadIdx.x;
    int n0 = blockIdx.x * 64;
    int m0 = blockIdx.y * 64;
    int t0 = m0 >> 6;
    int kk = tid & 15, mq = tid >> 4;
    int mg = tid & 15, ng = tid >> 4;

    float ar[4], br[4];
#pragma unroll
    for (int p = 0; p < 4; p++) {
        int r = p * 16 + mq;
        ar[p] = A[((size_t)r * Tt + t0) * Dd + kk];
        br[p] = Bw[(size_t)(n0 + r) * Dd + kk];
    }

    u64 acc[2][4];
#pragma unroll
    for (int p = 0; p < 2; p++)
#pragma unroll
        for (int q = 0; q < 4; q++) acc[p][q] = 0ull;

    for (int k0 = 0; k0 < Dd; k0 += 16) {
        __syncthreads();
#pragma unroll
        for (int p = 0; p < 4; p++) {
            As[kk][p * 16 + mq] = ar[p];
            Bs[kk][p * 16 + mq] = br[p];
        }
        __syncthreads();
        if (k0 + 16 < Dd) {
#pragma unroll
            for (int p = 0; p < 4; p++) {
                int r = p * 16 + mq;
                ar[p] = A[((size_t)r * Tt + t0) * Dd + k0 + 16 + kk];
                br[p] = Bw[(size_t)(n0 + r) * Dd + k0 + 16 + kk];
            }
        }
#pragma unroll
        for (int q = 0; q < 16; q++) {
            ulonglong2 a2 = *(const ulonglong2*)&As[q][mg * 4];
            float4 b4 = *(const float4*)&Bs[q][ng * 4];
            u64 bb0, bb1, bb2, bb3;
            DUP2(bb0, b4.x); DUP2(bb1, b4.y); DUP2(bb2, b4.z); DUP2(bb3, b4.w);
            FMA2(acc[0][0], a2.x, bb0); FMA2(acc[1][0], a2.y, bb0);
            FMA2(acc[0][1], a2.x, bb1); FMA2(acc[1][1], a2.y, bb1);
            FMA2(acc[0][2], a2.x, bb2); FMA2(acc[1][2], a2.y, bb2);
            FMA2(acc[0][3], a2.x, bb3); FMA2(acc[1][3], a2.y, bb3);
        }
    }
#pragma unroll
    for (int jj = 0; jj < 4; jj++) {
        int n = n0 + ng * 4 + jj;
        int g = n >> 10, j = n & 1023;
        float bv = bx[n] + bh[n];
        float v0, v1, v2, v3;
        UNPK2(v0, v1, acc[0][jj]);
        UNPK2(v2, v3, acc[1][jj]);
        float4 v = make_float4(v0 + bv, v1 + bv, v2 + bv, v3 + bv);
        *(float4*)&d_xg[((((size_t)t0 * Hh + j) << 2) + g) * Bb + mg * 4] = v;
    }
}

// ---------------- software grid barrier ----------------------------------------
__device__ __forceinline__ void grid_sync()
{
    __syncthreads();
    if (threadIdx.x == 0) {
        __threadfence();
        volatile unsigned* vg = &d_bgen;
        unsigned g = *vg;
        unsigned prev = atomicAdd(&d_bcount, 1u);
        if (prev == NCTA - 1) {
            d_bcount = 0u;
            __threadfence();
            atomicAdd(&d_bgen, 1u);
        } else {
            while (*vg == g) { __nanosleep(64); }
        }
        __threadfence();
    }
    __syncthreads();
}

__device__ __forceinline__ float sigm(float x) { return 1.0f / (1.0f + expf(-x)); }

// ---------------- persistent LSTM recurrence (tf32 mma.sync) --------------------
// 128 CTAs x 256 threads (8 warps). CTA owns 32 gate-cols (8 j x 4 gates), full
// batch N=64, full K=1024.  Warp w: m-strip = (w&1)*16, n-strip = (w>>1)*16.
// h staged via smem in 16 chunks of k=64 (double-buffered, pitch 72 = conflict
// free B-fragment LDS).  D -> smem -> register pointwise; c in registers.
#define HS_P 72
#define DS_P 68
__global__ void __launch_bounds__(256, 1) lstm_mma()
{
    __shared__ __align__(16) float hs[2][64 * HS_P];
    __shared__ __align__(16) float Ds[32 * DS_P];
    const int tid  = threadIdx.x;
    const int cta  = blockIdx.x;
    const int w    = tid >> 5, lane = tid & 31;
    const int g    = lane >> 2, tig = lane & 3;
    const int ms   = w & 1;
    const int n0   = (w >> 1) * 16;
    const int pb   = tid & 63;           // pointwise batch
    const int jl0  = tid >> 6;           // pointwise local j (and +4)
    const float4* Af = (const float4*)d_Af + ((size_t)cta * 2 + ms) * 4096 + lane;
    float cs[2] = {0.f, 0.f};

    for (int t = 0; t < Tt; t++) {
        const float* hcur = d_h2 + (size_t)(t & 1) * (Hh * Bb);
        float*       hnxt = d_h2 + (size_t)((t + 1) & 1) * (Hh * Bb);

        // prefetch xg for this thread's 2 (j, b) pairs: 8 scalars (DRAM, hidden)
        float xg0[4], xg1[4];
#pragma unroll
        for (int q = 0; q < 4; q++) {
            xg0[q] = d_xg[(((size_t)t * Hh + cta * 8 + jl0) * 4 + q) * Bb + pb];
            xg1[q] = d_xg[(((size_t)t * Hh + cta * 8 + jl0 + 4) * 4 + q) * Bb + pb];
        }

        float acc0[4] = {0.f, 0.f, 0.f, 0.f};
        float acc1[4] = {0.f, 0.f, 0.f, 0.f};

        // preload chunk 0 (64 k-rows x 64 b = 1024 float4)
        float4 st[4];
#pragma unroll
        for (int p = 0; p < 4; p++)
            st[p] = __ldcg((const float4*)hcur + p * 256 + tid);

#pragma unroll 1
        for (int ch = 0; ch < 16; ch++) {
            const int buf = ch & 1;
#pragma unroll
            for (int p = 0; p < 4; p++) {
                int idx = p * 256 + tid;
                *(float4*)&hs[buf][(idx >> 4) * HS_P + (idx & 15) * 4] = st[p];
            }
            __syncthreads();
            if (ch < 15) {
#pragma unroll
                for (int p = 0; p < 4; p++)
                    st[p] = __ldcg((const float4*)(hcur + (ch + 1) * 64 * 64) + p * 256 + tid);
            }
#pragma unroll
            for (int k8 = 0; k8 < 8; k8++) {
                float4 a4 = __ldg(&Af[(ch * 8 + k8) * 32]);
                unsigned a0 = __float_as_uint(a4.x), a1 = __float_as_uint(a4.y);
                unsigned a2 = __float_as_uint(a4.z), a3 = __float_as_uint(a4.w);
                const int kl = k8 * 8;
                unsigned b0 = __float_as_uint(hs[buf][(kl + tig) * HS_P + n0 + g]);
                unsigned b1 = __float_as_uint(hs[buf][(kl + tig + 4) * HS_P + n0 + g]);
                unsigned b2 = __float_as_uint(hs[buf][(kl + tig) * HS_P + n0 + 8 + g]);
                unsigned b3 = __float_as_uint(hs[buf][(kl + tig + 4) * HS_P + n0 + 8 + g]);
                MMA_TF32(acc0, a0, a1, a2, a3, b0, b1);
                MMA_TF32(acc1, a0, a1, a2, a3, b2, b3);
            }
        }

        // D fragments -> smem   (rows = local col m, cols = batch)
        {
            int r1 = ms * 16 + g, r2 = r1 + 8;
            *(float2*)&Ds[r1 * DS_P + n0 + tig * 2]     = make_float2(acc0[0], acc0[1]);
            *(float2*)&Ds[r2 * DS_P + n0 + tig * 2]     = make_float2(acc0[2], acc0[3]);
            *(float2*)&Ds[r1 * DS_P + n0 + 8 + tig * 2] = make_float2(acc1[0], acc1[1]);
            *(float2*)&Ds[r2 * DS_P + n0 + 8 + tig * 2] = make_float2(acc1[2], acc1[3]);
        }
        __syncthreads();

        // pointwise: 2 (j, b) pairs per thread; c in registers
#pragma unroll
        for (int pp = 0; pp < 2; pp++) {
            int jl = jl0 + pp * 4;
            const float* xf = pp ? xg1 : xg0;
            float gi = Ds[(jl * 4 + 0) * DS_P + pb] + xf[0];
            float gf = Ds[(jl * 4 + 1) * DS_P + pb] + xf[1];
            float gg = Ds[(jl * 4 + 2) * DS_P + pb] + xf[2];
            float go = Ds[(jl * 4 + 3) * DS_P + pb] + xf[3];
            float si = sigm(gi), sf = sigm(gf), sg = sigm(gg), so = sigm(go);
            float cn = cs[pp] * sf + si * sg;      // NOTE: sigmoid cell gate (per ref)
            cs[pp] = cn;
            float hn = so * tanhf(cn);
            int j = cta * 8 + jl;
            d_hsJ[((size_t)j * Tt + t) * 64 + pb] = hn;             // full precision
            __stcg(&hnxt[j * 64 + pb], __uint_as_float(tf32r(hn))); // tf32-rounded
        }
        grid_sync();
    }
}

// ---------------- GEMM 3 (TN): out[b][t][d] = hs . WoutT + bout -----------------
__global__ void __launch_bounds__(256) gemm_out(
    const float* __restrict__ bias, float* __restrict__ outp)
{
    __shared__ __align__(16) float As[16 * 64];
    __shared__ __align__(16) float Bs[16 * 64];
    int tid = threadIdx.x;
    int n0 = blockIdx.x * 64;      // d
    int m0 = blockIdx.y * 64;      // m'
    int t0 = m0 >> 6;
    int lk = tid >> 4, lc = (tid & 15) * 4;
    int mg = tid & 15, ng = tid >> 4;

    float4 av = *(const float4*)&d_hsJ[(size_t)lk * Mm + m0 + lc];
    float4 bv = *(const float4*)&d_WoT[(size_t)lk * Dd + n0 + lc];

    u64 acc[2][4];
#pragma unroll
    for (int p = 0; p < 2; p++)
#pragma unroll
        for (int q = 0; q < 4; q++) acc[p][q] = 0ull;

    for (int k0 = 0; k0 < Hh; k0 += 16) {
        __syncthreads();
        *(float4*)&As[lk * 64 + lc] = av;
        *(float4*)&Bs[lk * 64 + lc] = bv;
        __syncthreads();
        if (k0 + 16 < Hh) {
            av = *(const float4*)&d_hsJ[(size_t)(k0 + 16 + lk) * Mm + m0 + lc];
            bv = *(const float4*)&d_WoT[(size_t)(k0 + 16 + lk) * Dd + n0 + lc];
        }
#pragma unroll
        for (int q = 0; q < 16; q++) {
            ulonglong2 a2 = *(const ulonglong2*)&As[q * 64 + mg * 4];
            float4 b4 = *(const float4*)&Bs[q * 64 + ng * 4];
            u64 bb0, bb1, bb2, bb3;
            DUP2(bb0, b4.x); DUP2(bb1, b4.y); DUP2(bb2, b4.z); DUP2(bb3, b4.w);
            FMA2(acc[0][0], a2.x, bb0); FMA2(acc[1][0], a2.y, bb0);
            FMA2(acc[0][1], a2.x, bb1); FMA2(acc[1][1], a2.y, bb1);
            FMA2(acc[0][2], a2.x, bb2); FMA2(acc[1][2], a2.y, bb2);
            FMA2(acc[0][3], a2.x, bb3); FMA2(acc[1][3], a2.y, bb3);
        }
    }
    float4 b4 = *(const float4*)&bias[n0 + ng * 4];
    float r[4][4];
#pragma unroll
    for (int q = 0; q < 4; q++) {
        UNPK2(r[0][q], r[1][q], acc[0][q]);
        UNPK2(r[2][q], r[3][q], acc[1][q]);
    }
#pragma unroll
    for (int i = 0; i < 4; i++) {
        int b = mg * 4 + i;
        float4 v = make_float4(r[i][0] + b4.x, r[i][1] + b4.y,
                               r[i][2] + b4.z, r[i][3] + b4.w);
        *(float4*)&outp[((size_t)b * Tt + t0) * Dd + n0 + ng * 4] = v;
    }
}

// ---------------- hidden = tanh(hs), [j][m'] -> [b][t][j] ----------------------
__global__ void tanhT_k(float* __restrict__ outH)
{
    __shared__ float tile[32][33];
    int m0 = blockIdx.x * 32;
    int j0 = blockIdx.y * 32;
    int tx = threadIdx.x, ty = threadIdx.y;
#pragma unroll
    for (int i = 0; i < 32; i += 8)
        tile[ty + i][tx] = d_hsJ[(size_t)(j0 + ty + i) * Mm + m0 + tx];
    __syncthreads();
    int t0 = m0 >> 6;
    int bbase = m0 & 63;
#pragma unroll
    for (int i = 0; i < 32; i += 8) {
        int mp = ty + i;
        int b = bbase + mp;
        outH[((size_t)b * Tt + t0) * Hh + j0 + tx] = tanhf(tile[tx][mp]);
    }
}

// ---------------- launch --------------------------------------------------------
extern "C" void kernel_launch(void* const* d_in, const int* in_sizes, int n_in,
                              void* d_out, int out_size)
{
    (void)in_sizes; (void)n_in; (void)out_size;
    const float* inp = (const float*)d_in[0];
    const float* Wx  = (const float*)d_in[1];
    const float* bx  = (const float*)d_in[2];
    const float* Wh  = (const float*)d_in[3];
    const float* bh  = (const float*)d_in[4];
    const float* Wo  = (const float*)d_in[5];
    const float* bo  = (const float*)d_in[6];
    float* out = (float*)d_out;
    float* outHidden = out + (size_t)Bb * Tt * Dd;

    init_k<<<512, 256>>>();
    transpose_wo<<<dim3(Hh / 32, Dd / 32), dim3(32, 8)>>>(Wo);
    pack_af<<<4096, 256>>>(Wh);
    gemm_xg<<<dim3(Gg / 64, Mm / 64), 256>>>(inp, Wx, bx, bh);
    lstm_mma<<<NCTA, 256>>>();
    gemm_out<<<dim3(Dd / 64, Mm / 64), 256>>>(bo, out);
    tanhT_k<<<dim3(Mm / 32, Hh / 32), dim3(32, 8)>>>(outHidden);
}

// round 6
// speedup vs baseline: 2.0924x; 1.2132x over previous
#include <cuda_runtime.h>
#include <math.h>

// Problem dims
#define Bb   64
#define Tt   512
#define Dd   256
#define Hh   1024
#define Gg   4096          // 4*H
#define Mm   32768         // B*T
#define NCTA 128

// ---------------- scratch (__device__ globals; no dynamic allocation) ----------
__device__ float d_xg[(size_t)Tt * Gg * Bb];      // [t][m=j*4+g][b]   512 MB
__device__ float d_Af[(size_t)Gg * Hh];           // Wh tf32 A-fragments (lstm), 16 MB
__device__ float d_Axf[(size_t)Gg * Dd];          // Wx tf32 A-fragments, 4 MB
__device__ float d_Wof[(size_t)Dd * Hh];          // Wout tf32 A-fragments, 1 MB
__device__ float d_hsJ[(size_t)Hh * Mm];          // [j][m'] , m'=t*64+b   128 MB
__device__ float d_outT[(size_t)Dd * Mm];         // out head, [d][m']     32 MB
__device__ float d_h2[2 * Hh * Bb];               // double-buffered h, [buf][k][b]
__device__ unsigned d_bcount;
__device__ unsigned d_bgen;

__device__ __forceinline__ unsigned tf32r(float x)
{
    unsigned u;
    asm("cvt.rna.tf32.f32 %0, %1;" : "=r"(u) : "f"(x));
    return u;
}

// tf32 mma: D(m16n8) += A(m16k8) * B(k8n8)
#define MMA_TF32(d, a0, a1, a2, a3, b0, b1)                                     \
    asm volatile("mma.sync.aligned.m16n8k8.row.col.f32.tf32.tf32.f32 "          \
                 "{%0,%1,%2,%3}, {%4,%5,%6,%7}, {%8,%9}, {%0,%1,%2,%3};"        \
                 : "+f"(d[0]), "+f"(d[1]), "+f"(d[2]), "+f"(d[3])               \
                 : "r"(a0), "r"(a1), "r"(a2), "r"(a3), "r"(b0), "r"(b1))

// ---------------- init: zero h state, reset barrier ----------------------------
__global__ void init_k()
{
    int i = blockIdx.x * blockDim.x + threadIdx.x;
    if (i < 2 * Hh * Bb) d_h2[i] = 0.0f;
    if (i == 0) { d_bcount = 0u; d_bgen = 0u; }
}

// ---------------- pack Wh into per-warp tf32 A-fragments (lstm) -----------------
// float4 index i: lane=i&31, kc=(i>>5)&127, ms=(i>>12)&1, cb=i>>13
__global__ void pack_af(const float* __restrict__ Wh)
{
    size_t i = (size_t)blockIdx.x * blockDim.x + threadIdx.x;   // 1,048,576
    int lane = i & 31;
    int kc   = (i >> 5) & 127;
    int ms   = (i >> 12) & 1;
    int cb   = (int)(i >> 13);
    int g = lane >> 2, tig = lane & 3;
    int m1 = ms * 16 + g, m2 = m1 + 8;
    int r1 = (m1 & 3) * Hh + cb * 8 + (m1 >> 2);
    int r2 = (m2 & 3) * Hh + cb * 8 + (m2 >> 2);
    int k0 = kc * 8;
    float4 v;
    v.x = __uint_as_float(tf32r(Wh[(size_t)r1 * Hh + k0 + tig]));
    v.y = __uint_as_float(tf32r(Wh[(size_t)r2 * Hh + k0 + tig]));
    v.z = __uint_as_float(tf32r(Wh[(size_t)r1 * Hh + k0 + tig + 4]));
    v.w = __uint_as_float(tf32r(Wh[(size_t)r2 * Hh + k0 + tig + 4]));
    ((float4*)d_Af)[i] = v;
}

// ---------------- pack Wx into tf32 A-fragments for gemm_xg --------------------
// float4 index i: lane=i&31, k8=(i>>5)&31, ws=(i>>10)&7, gb=i>>13 (0..31)
// local row m = gb*128 + ws*16 + ...; source Wx row = (m&3)*1024 + (m>>2)
__global__ void pack_wxf(const float* __restrict__ Wx)
{
    size_t i = (size_t)blockIdx.x * blockDim.x + threadIdx.x;   // 262,144
    int lane = i & 31;
    int k8   = (i >> 5) & 31;
    int ws   = (i >> 10) & 7;
    int gb   = (int)(i >> 13);
    int g = lane >> 2, tig = lane & 3;
    int m1 = gb * 128 + ws * 16 + g;
    int m2 = m1 + 8;
    int r1 = (m1 & 3) * Hh + (m1 >> 2);
    int r2 = (m2 & 3) * Hh + (m2 >> 2);
    int k0 = k8 * 8;
    float4 v;
    v.x = __uint_as_float(tf32r(Wx[(size_t)r1 * Dd + k0 + tig]));
    v.y = __uint_as_float(tf32r(Wx[(size_t)r2 * Dd + k0 + tig]));
    v.z = __uint_as_float(tf32r(Wx[(size_t)r1 * Dd + k0 + tig + 4]));
    v.w = __uint_as_float(tf32r(Wx[(size_t)r2 * Dd + k0 + tig + 4]));
    ((float4*)d_Axf)[i] = v;
}

// ---------------- pack Wout into tf32 A-fragments for gemm_out ------------------
// float4 index i: lane=i&31, k8=(i>>5)&127, s=i>>12 (0..15).  A[m=d][k=h]=Wout[d][h]
__global__ void pack_wof(const float* __restrict__ Wo)
{
    size_t i = (size_t)blockIdx.x * blockDim.x + threadIdx.x;   // 65,536
    int lane = i & 31;
    int k8   = (i >> 5) & 127;
    int s    = (int)(i >> 12);
    int g = lane >> 2, tig = lane & 3;
    int d1 = s * 16 + g, d2 = d1 + 8;
    int k0 = k8 * 8;
    float4 v;
    v.x = __uint_as_float(tf32r(Wo[(size_t)d1 * Hh + k0 + tig]));
    v.y = __uint_as_float(tf32r(Wo[(size_t)d2 * Hh + k0 + tig]));
    v.z = __uint_as_float(tf32r(Wo[(size_t)d1 * Hh + k0 + tig + 4]));
    v.w = __uint_as_float(tf32r(Wo[(size_t)d2 * Hh + k0 + tig + 4]));
    ((float4*)d_Wof)[i] = v;
}

// ---------------- GEMM 1 (tf32 mma): xg = inputs . Wx^T + bx + bh ---------------
// Grid (32 gate-blocks, 4).  CTA: 128 gate-rows x 64 batch, K=256, TWO t per pass.
// Inputs staged [b][k] pitch 260 (B-frag reads bank-conflict-free: 4g+tig).
#define XP 260
__global__ void __launch_bounds__(256) gemm_xg_mma(
    const float* __restrict__ inp, const float* __restrict__ bx,
    const float* __restrict__ bh)
{
    extern __shared__ float Bsm[];            // 2 * 64 * XP floats
    const int tid = threadIdx.x, w = tid >> 5, lane = tid & 31;
    const int g = lane >> 2, tig = lane & 3;
    const int gb = blockIdx.x;
    const int m1 = gb * 128 + w * 16 + g, m2 = m1 + 8;
    const int r1 = (m1 & 3) * Hh + (m1 >> 2), r2 = (m2 & 3) * Hh + (m2 >> 2);
    const float bias1 = bx[r1] + bh[r1];
    const float bias2 = bx[r2] + bh[r2];
    const float4* Af = (const float4*)d_Axf + (size_t)(gb * 8 + w) * 1024 + lane;
    const int brow = w * 8 + (lane >> 2);
    const int bq = lane & 3;

    for (int t0 = blockIdx.y * 2; t0 < Tt; t0 += 8) {
        // load two input t-slices -> smem [b][k]
#pragma unroll
        for (int sl = 0; sl < 2; sl++) {
            const float4* src = (const float4*)(inp + ((size_t)brow * Tt + t0 + sl) * Dd);
            float* dst = Bsm + sl * 64 * XP + brow * XP;
#pragma unroll
            for (int i2 = 0; i2 < 16; i2++)
                *(float4*)&dst[(i2 * 4 + bq) * 4] = __ldg(&src[i2 * 4 + bq]);
        }
        __syncthreads();

        float acc[2][8][4];
#pragma unroll
        for (int sl = 0; sl < 2; sl++)
#pragma unroll
            for (int nb = 0; nb < 8; nb++)
#pragma unroll
                for (int q = 0; q < 4; q++) acc[sl][nb][q] = 0.f;

#pragma unroll 4
        for (int k8 = 0; k8 < 32; k8++) {
            float4 a4 = __ldg(&Af[k8 * 32]);
            unsigned a0 = __float_as_uint(a4.x), a1 = __float_as_uint(a4.y);
            unsigned a2 = __float_as_uint(a4.z), a3 = __float_as_uint(a4.w);
            const int kl = k8 * 8;
#pragma unroll
            for (int nb = 0; nb < 8; nb++) {
#pragma unroll
                for (int sl = 0; sl < 2; sl++) {
                    const float* bp = Bsm + sl * 64 * XP + (nb * 8 + g) * XP + kl + tig;
                    unsigned b0 = __float_as_uint(bp[0]);
                    unsigned b1 = __float_as_uint(bp[4]);
                    MMA_TF32(acc[sl][nb], a0, a1, a2, a3, b0, b1);
                }
            }
        }
#pragma unroll
        for (int sl = 0; sl < 2; sl++) {
            int t = t0 + sl;
#pragma unroll
            for (int nb = 0; nb < 8; nb++) {
                *(float2*)&d_xg[((size_t)t * Gg + m1) * 64 + nb * 8 + tig * 2] =
                    make_float2(acc[sl][nb][0] + bias1, acc[sl][nb][1] + bias1);
                *(float2*)&d_xg[((size_t)t * Gg + m2) * 64 + nb * 8 + tig * 2] =
                    make_float2(acc[sl][nb][2] + bias2, acc[sl][nb][3] + bias2);
            }
        }
        __syncthreads();
    }
}

// ---------------- software grid barrier ----------------------------------------
__device__ __forceinline__ void grid_sync()
{
    __syncthreads();
    if (threadIdx.x == 0) {
        __threadfence();
        volatile unsigned* vg = &d_bgen;
        unsigned g = *vg;
        unsigned prev = atomicAdd(&d_bcount, 1u);
        if (prev == NCTA - 1) {
            d_bcount = 0u;
            __threadfence();
            atomicAdd(&d_bgen, 1u);
        } else {
            while (*vg == g) { __nanosleep(64); }
        }
        __threadfence();
    }
    __syncthreads();
}

__device__ __forceinline__ float sigm(float x) { return 1.0f / (1.0f + expf(-x)); }

// ---------------- persistent LSTM recurrence (tf32 mma.sync) --------------------
#define HS_P 72
#define DS_P 68
__global__ void __launch_bounds__(256, 1) lstm_mma()
{
    __shared__ __align__(16) float hs[2][64 * HS_P];
    __shared__ __align__(16) float Ds[32 * DS_P];
    const int tid  = threadIdx.x;
    const int cta  = blockIdx.x;
    const int w    = tid >> 5, lane = tid & 31;
    const int g    = lane >> 2, tig = lane & 3;
    const int ms   = w & 1;
    const int n0   = (w >> 1) * 16;
    const int pb   = tid & 63;
    const int jl0  = tid >> 6;
    const float4* Af = (const float4*)d_Af + ((size_t)cta * 2 + ms) * 4096 + lane;
    float cs[2] = {0.f, 0.f};

    for (int t = 0; t < Tt; t++) {
        const float* hcur = d_h2 + (size_t)(t & 1) * (Hh * Bb);
        float*       hnxt = d_h2 + (size_t)((t + 1) & 1) * (Hh * Bb);

        float xg0[4], xg1[4];
#pragma unroll
        for (int q = 0; q < 4; q++) {
            xg0[q] = d_xg[(((size_t)t * Hh + cta * 8 + jl0) * 4 + q) * Bb + pb];
            xg1[q] = d_xg[(((size_t)t * Hh + cta * 8 + jl0 + 4) * 4 + q) * Bb + pb];
        }

        float acc0[4] = {0.f, 0.f, 0.f, 0.f};
        float acc1[4] = {0.f, 0.f, 0.f, 0.f};

        float4 st[4];
#pragma unroll
        for (int p = 0; p < 4; p++)
            st[p] = __ldcg((const float4*)hcur + p * 256 + tid);

#pragma unroll 1
        for (int ch = 0; ch < 16; ch++) {
            const int buf = ch & 1;
#pragma unroll
            for (int p = 0; p < 4; p++) {
                int idx = p * 256 + tid;
                *(float4*)&hs[buf][(idx >> 4) * HS_P + (idx & 15) * 4] = st[p];
            }
            __syncthreads();
            if (ch < 15) {
#pragma unroll
                for (int p = 0; p < 4; p++)
                    st[p] = __ldcg((const float4*)(hcur + (ch + 1) * 64 * 64) + p * 256 + tid);
            }
#pragma unroll
            for (int k8 = 0; k8 < 8; k8++) {
                float4 a4 = __ldg(&Af[(ch * 8 + k8) * 32]);
                unsigned a0 = __float_as_uint(a4.x), a1 = __float_as_uint(a4.y);
                unsigned a2 = __float_as_uint(a4.z), a3 = __float_as_uint(a4.w);
                const int kl = k8 * 8;
                unsigned b0 = __float_as_uint(hs[buf][(kl + tig) * HS_P + n0 + g]);
                unsigned b1 = __float_as_uint(hs[buf][(kl + tig + 4) * HS_P + n0 + g]);
                unsigned b2 = __float_as_uint(hs[buf][(kl + tig) * HS_P + n0 + 8 + g]);
                unsigned b3 = __float_as_uint(hs[buf][(kl + tig + 4) * HS_P + n0 + 8 + g]);
                MMA_TF32(acc0, a0, a1, a2, a3, b0, b1);
                MMA_TF32(acc1, a0, a1, a2, a3, b2, b3);
            }
        }

        {
            int r1 = ms * 16 + g, r2 = r1 + 8;
            *(float2*)&Ds[r1 * DS_P + n0 + tig * 2]     = make_float2(acc0[0], acc0[1]);
            *(float2*)&Ds[r2 * DS_P + n0 + tig * 2]     = make_float2(acc0[2], acc0[3]);
            *(float2*)&Ds[r1 * DS_P + n0 + 8 + tig * 2] = make_float2(acc1[0], acc1[1]);
            *(float2*)&Ds[r2 * DS_P + n0 + 8 + tig * 2] = make_float2(acc1[2], acc1[3]);
        }
        __syncthreads();

#pragma unroll
        for (int pp = 0; pp < 2; pp++) {
            int jl = jl0 + pp * 4;
            const float* xf = pp ? xg1 : xg0;
            float gi = Ds[(jl * 4 + 0) * DS_P + pb] + xf[0];
            float gf = Ds[(jl * 4 + 1) * DS_P + pb] + xf[1];
            float gg = Ds[(jl * 4 + 2) * DS_P + pb] + xf[2];
            float go = Ds[(jl * 4 + 3) * DS_P + pb] + xf[3];
            float si = sigm(gi), sf = sigm(gf), sg = sigm(gg), so = sigm(go);
            float cn = cs[pp] * sf + si * sg;      // NOTE: sigmoid cell gate (per ref)
            cs[pp] = cn;
            float hn = so * tanhf(cn);
            int j = cta * 8 + jl;
            d_hsJ[((size_t)j * Tt + t) * 64 + pb] = hn;
            __stcg(&hnxt[j * 64 + pb], __uint_as_float(tf32r(hn)));
        }
        grid_sync();
    }
}

// ---------------- GEMM 3 (tf32 mma): outT[d][m'] = Wout . hs --------------------
// One CTA per t.  A = Wout frags (M=256 d), B = hs chunk smem [k][b] pitch 72.
__global__ void __launch_bounds__(256) gemm_out_mma()
{
    __shared__ __align__(16) float hsm[2][64 * HS_P];
    const int tid = threadIdx.x, w = tid >> 5, lane = tid & 31;
    const int g = lane >> 2, tig = lane & 3;
    const int t = blockIdx.x;
    const int lk = tid >> 4, lf = tid & 15;
    const float4* Af1 = (const float4*)d_Wof + (size_t)w * 128 * 32 + lane;
    const float4* Af2 = (const float4*)d_Wof + (size_t)(w + 8) * 128 * 32 + lane;

    float acc[2][8][4];
#pragma unroll
    for (int sh = 0; sh < 2; sh++)
#pragma unroll
        for (int nb = 0; nb < 8; nb++)
#pragma unroll
            for (int q = 0; q < 4; q++) acc[sh][nb][q] = 0.f;

    float4 st[4];
#pragma unroll
    for (int p = 0; p < 4; p++) {
        int k = p * 16 + lk;
        st[p] = __ldcg((const float4*)&d_hsJ[((size_t)k * Tt + t) * 64 + lf * 4]);
    }

#pragma unroll 1
    for (int ch = 0; ch < 16; ch++) {
        const int buf = ch & 1;
#pragma unroll
        for (int p = 0; p < 4; p++)
            *(float4*)&hsm[buf][(p * 16 + lk) * HS_P + lf * 4] = st[p];
        __syncthreads();
        if (ch < 15) {
#pragma unroll
            for (int p = 0; p < 4; p++) {
                int k = (ch + 1) * 64 + p * 16 + lk;
                st[p] = __ldcg((const float4*)&d_hsJ[((size_t)k * Tt + t) * 64 + lf * 4]);
            }
        }
#pragma unroll
        for (int k8 = 0; k8 < 8; k8++) {
            const int kg = ch * 8 + k8;
            const int kl = k8 * 8;
            float4 af1 = __ldg(&Af1[kg * 32]);
            float4 af2 = __ldg(&Af2[kg * 32]);
            unsigned a10 = __float_as_uint(af1.x), a11 = __float_as_uint(af1.y);
            unsigned a12 = __float_as_uint(af1.z), a13 = __float_as_uint(af1.w);
            unsigned a20 = __float_as_uint(af2.x), a21 = __float_as_uint(af2.y);
            unsigned a22 = __float_as_uint(af2.z), a23 = __float_as_uint(af2.w);
#pragma unroll
            for (int nb = 0; nb < 8; nb++) {
                unsigned b0 = __float_as_uint(hsm[buf][(kl + tig) * HS_P + nb * 8 + g]);
                unsigned b1 = __float_as_uint(hsm[buf][(kl + tig + 4) * HS_P + nb * 8 + g]);
                MMA_TF32(acc[0][nb], a10, a11, a12, a13, b0, b1);
                MMA_TF32(acc[1][nb], a20, a21, a22, a23, b0, b1);
            }
        }
        __syncthreads();
    }

#pragma unroll
    for (int sh = 0; sh < 2; sh++) {
        int dbase = (sh ? (w + 8) : w) * 16;
        int d1 = dbase + g, d2 = d1 + 8;
#pragma unroll
        for (int nb = 0; nb < 8; nb++) {
            int bcol = nb * 8 + tig * 2;
            *(float2*)&d_outT[(size_t)d1 * Mm + t * 64 + bcol] =
                make_float2(acc[sh][nb][0], acc[sh][nb][1]);
            *(float2*)&d_outT[(size_t)d2 * Mm + t * 64 + bcol] =
                make_float2(acc[sh][nb][2], acc[sh][nb][3]);
        }
    }
}

// ---------------- out = outT^T + bias: [d][m'] -> [b][t][d] ---------------------
__global__ void outT_k(const float* __restrict__ bo, float* __restrict__ outp)
{
    __shared__ float tile[32][33];
    int m0 = blockIdx.x * 32;
    int d0 = blockIdx.y * 32;
    int tx = threadIdx.x, ty = threadIdx.y;
#pragma unroll
    for (int i = 0; i < 32; i += 8)
        tile[ty + i][tx] = d_outT[(size_t)(d0 + ty + i) * Mm + m0 + tx];
    __syncthreads();
    int t0 = m0 >> 6;
    int bbase = m0 & 63;
    float bv = bo[d0 + tx];
#pragma unroll
    for (int i = 0; i < 32; i += 8) {
        int b = bbase + ty + i;
        outp[((size_t)b * Tt + t0) * Dd + d0 + tx] = tile[tx][ty + i] + bv;
    }
}

// ---------------- hidden = tanh(hs), [j][m'] -> [b][t][j] ----------------------
__global__ void tanhT_k(float* __restrict__ outH)
{
    __shared__ float tile[32][33];
    int m0 = blockIdx.x * 32;
    int j0 = blockIdx.y * 32;
    int tx = threadIdx.x, ty = threadIdx.y;
#pragma unroll
    for (int i = 0; i < 32; i += 8)
        tile[ty + i][tx] = d_hsJ[(size_t)(j0 + ty + i) * Mm + m0 + tx];
    __syncthreads();
    int t0 = m0 >> 6;
    int bbase = m0 & 63;
#pragma unroll
    for (int i = 0; i < 32; i += 8) {
        int mp = ty + i;
        int b = bbase + mp;
        outH[((size_t)b * Tt + t0) * Hh + j0 + tx] = tanhf(tile[tx][mp]);
    }
}

// ---------------- launch --------------------------------------------------------
extern "C" void kernel_launch(void* const* d_in, const int* in_sizes, int n_in,
                              void* d_out, int out_size)
{
    (void)in_sizes; (void)n_in; (void)out_size;
    const float* inp = (const float*)d_in[0];
    const float* Wx  = (const float*)d_in[1];
    const float* bx  = (const float*)d_in[2];
    const float* Wh  = (const float*)d_in[3];
    const float* bh  = (const float*)d_in[4];
    const float* Wo  = (const float*)d_in[5];
    const float* bo  = (const float*)d_in[6];
    float* out = (float*)d_out;
    float* outHidden = out + (size_t)Bb * Tt * Dd;

    static int smem_set = 0;
    int xg_smem = 2 * 64 * XP * sizeof(float);   // 133,120 B -> 1 CTA/SM
    if (!smem_set) {
        cudaFuncSetAttribute(gemm_xg_mma,
                             cudaFuncAttributeMaxDynamicSharedMemorySize, xg_smem);
        smem_set = 1;
    }

    init_k<<<512, 256>>>();
    pack_af<<<4096, 256>>>(Wh);
    pack_wxf<<<1024, 256>>>(Wx);
    pack_wof<<<256, 256>>>(Wo);
    gemm_xg_mma<<<dim3(32, 4), 256, xg_smem>>>(inp, bx, bh);
    lstm_mma<<<NCTA, 256>>>();
    gemm_out_mma<<<Tt, 256>>>();
    tanhT_k<<<dim3(Mm / 32, Hh / 32), dim3(32, 8)>>>(outHidden);
    outT_k<<<dim3(Mm / 32, Dd / 32), dim3(32, 8)>>>(bo, out);
}